// round 7
// baseline (speedup 1.0000x reference)
#include <cuda_runtime.h>
#include <cuda_fp16.h>

// Problem constants
#define HOPS  3
#define VOCAB 50257
#define EMB   128
#define MEM   256   // memory slots (M)
#define BATCH 16    // batch (B)
#define SENT  64    // sentence length (S)

#define TBL_ELEMS   ((size_t)VOCAB * EMB)
#define TBL_ITEMS8  (TBL_ELEMS / 8)        // 804112 uint4 items per table

// fp16 copies of tables C1..C3 (C0 never needed: hop-0 softmax of zero logits
// is exactly uniform). 38.6 MB static scratch.
__device__ __align__(16) __half g_Ch[3ULL * VOCAB * EMB];
// E[t][b][m][d] = sum_s C[t+1][story[m][b][s]][d], fp16 (3.1 MB).
__device__ __align__(16) __half g_Eh[3][BATCH][MEM][EMB];
// hop state u, fp32
__device__ __align__(16) float g_u[BATCH][EMB];

// ---------------------------------------------------------------------------
// Helpers
// ---------------------------------------------------------------------------
__device__ __forceinline__ void convert_item(const float* __restrict__ C,
                                             int tbl, size_t i) {
    const float4* __restrict__ src =
        (const float4*)(C + (size_t)(tbl + 1) * TBL_ELEMS);
    float4 a = __ldg(src + 2 * i);
    float4 b = __ldg(src + 2 * i + 1);
    __half2 h0 = __floats2half2_rn(a.x, a.y);
    __half2 h1 = __floats2half2_rn(a.z, a.w);
    __half2 h2 = __floats2half2_rn(b.x, b.y);
    __half2 h3 = __floats2half2_rn(b.z, b.w);
    uint4 o;
    o.x = *reinterpret_cast<unsigned int*>(&h0);
    o.y = *reinterpret_cast<unsigned int*>(&h1);
    o.z = *reinterpret_cast<unsigned int*>(&h2);
    o.w = *reinterpret_cast<unsigned int*>(&h3);
    ((uint4*)g_Ch)[(size_t)tbl * TBL_ITEMS8 + i] = o;
}

// One (t,b,m) gather-sum unit per warp, fp16 table, fp32 accumulation.
__device__ __forceinline__ void gather_unit(const int* __restrict__ story,
                                            int t, int b, int m, int lane) {
    const int* toks = story + ((size_t)m * BATCH + b) * SENT;
    const int tok_lo = toks[lane];
    const int tok_hi = toks[lane + 32];
    const uint2* __restrict__ tab =
        (const uint2*)g_Ch + (size_t)t * VOCAB * (EMB / 4);

    float4 a0 = make_float4(0.f, 0.f, 0.f, 0.f);
    float4 a1 = make_float4(0.f, 0.f, 0.f, 0.f);
#pragma unroll
    for (int s = 0; s < 32; s++) {
        int tok = __shfl_sync(0xffffffffu, tok_lo, s);
        uint2 v = __ldg(tab + (size_t)tok * 32 + lane);
        float2 f0 = __half22float2(*reinterpret_cast<__half2*>(&v.x));
        float2 f1 = __half22float2(*reinterpret_cast<__half2*>(&v.y));
        a0.x += f0.x; a0.y += f0.y; a0.z += f1.x; a0.w += f1.y;
    }
#pragma unroll
    for (int s = 0; s < 32; s++) {
        int tok = __shfl_sync(0xffffffffu, tok_hi, s);
        uint2 v = __ldg(tab + (size_t)tok * 32 + lane);
        float2 f0 = __half22float2(*reinterpret_cast<__half2*>(&v.x));
        float2 f1 = __half22float2(*reinterpret_cast<__half2*>(&v.y));
        a1.x += f0.x; a1.y += f0.y; a1.z += f1.x; a1.w += f1.y;
    }
    __half2 o0 = __floats2half2_rn(a0.x + a1.x, a0.y + a1.y);
    __half2 o1 = __floats2half2_rn(a0.z + a1.z, a0.w + a1.w);
    uint2 o;
    o.x = *reinterpret_cast<unsigned int*>(&o0);
    o.y = *reinterpret_cast<unsigned int*>(&o1);
    ((uint2*)g_Eh[t][b][m])[lane] = o;
}

// hop0 for batch b with 128 threads: g_u[b] = mean_m E0[b][m]
__device__ __forceinline__ void hop0_128(int b) {
    __shared__ float4 wpart0[4][32];
    const int tid = threadIdx.x, w = tid >> 5, lane = tid & 31;
    const uint2* __restrict__ E0 = (const uint2*)g_Eh[0][b];
    float4 acc = make_float4(0.f, 0.f, 0.f, 0.f);
#pragma unroll 8
    for (int k = 0; k < 64; k++) {
        uint2 v = E0[(size_t)(w * 64 + k) * 32 + lane];
        float2 f0 = __half22float2(*reinterpret_cast<__half2*>(&v.x));
        float2 f1 = __half22float2(*reinterpret_cast<__half2*>(&v.y));
        acc.x += f0.x; acc.y += f0.y; acc.z += f1.x; acc.w += f1.y;
    }
    wpart0[w][lane] = acc;
    __syncthreads();
    if (tid < 32) {
        float4 a = wpart0[0][tid];
#pragma unroll
        for (int i = 1; i < 4; i++) {
            float4 c = wpart0[i][tid];
            a.x += c.x; a.y += c.y; a.z += c.z; a.w += c.w;
        }
        a.x *= (1.f / MEM); a.y *= (1.f / MEM); a.z *= (1.f / MEM); a.w *= (1.f / MEM);
        ((float4*)g_u[b])[tid] = a;
    }
}

// One attention hop for batch b with 128 threads:
//   prob = softmax_m( E[hp-1][b] . u_in ) ;  dst = u_in + sum_m prob[m]*E[hp][b][m]
__device__ __forceinline__ void hop_128(int hp, int b, float* __restrict__ dst) {
    __shared__ float4 us[32];
    __shared__ float  prob[MEM];
    __shared__ float4 wpart[4][32];
    __shared__ float  red[4];

    const int tid = threadIdx.x, w = tid >> 5, lane = tid & 31;
    const uint2* __restrict__ Ep = (const uint2*)g_Eh[hp - 1][b];
    const uint2* __restrict__ Ec = (const uint2*)g_Eh[hp][b];

    if (tid < 32) us[tid] = ((const float4*)g_u[b])[tid];
    __syncthreads();

    // logits: 4 lanes per slot, 32 slots per pass, 8 passes (64 loads/lane)
    const int q = lane & 3, sl = lane >> 2;
#pragma unroll
    for (int pass = 0; pass < 8; pass++) {
        const int m = pass * 32 + w * 8 + sl;
        float pd = 0.f;
#pragma unroll
        for (int j = 0; j < 8; j++) {
            uint2 v = Ep[(size_t)m * 32 + q + 4 * j];
            float2 f0 = __half22float2(*reinterpret_cast<__half2*>(&v.x));
            float2 f1 = __half22float2(*reinterpret_cast<__half2*>(&v.y));
            float4 uu = us[q + 4 * j];
            pd += f0.x * uu.x + f0.y * uu.y + f1.x * uu.z + f1.y * uu.w;
        }
        pd += __shfl_xor_sync(0xffffffffu, pd, 1);
        pd += __shfl_xor_sync(0xffffffffu, pd, 2);
        if (q == 0) prob[m] = pd;
    }
    __syncthreads();

    // softmax over 256 values, 2 per thread
    float x0 = prob[tid], x1 = prob[tid + 128];
    float mx = fmaxf(x0, x1);
#pragma unroll
    for (int off = 16; off; off >>= 1)
        mx = fmaxf(mx, __shfl_xor_sync(0xffffffffu, mx, off));
    if (lane == 0) red[w] = mx;
    __syncthreads();
    mx = fmaxf(fmaxf(red[0], red[1]), fmaxf(red[2], red[3]));
    __syncthreads();

    float e0 = __expf(x0 - mx), e1 = __expf(x1 - mx);
    float s = e0 + e1;
#pragma unroll
    for (int off = 16; off; off >>= 1)
        s += __shfl_xor_sync(0xffffffffu, s, off);
    if (lane == 0) red[w] = s;
    __syncthreads();
    float tot = red[0] + red[1] + red[2] + red[3];
    float inv = 1.f / tot;
    prob[tid] = e0 * inv;
    prob[tid + 128] = e1 * inv;
    __syncthreads();

    // weighted sum: warp w owns 64 slots
    float4 acc = make_float4(0.f, 0.f, 0.f, 0.f);
#pragma unroll 8
    for (int k = 0; k < 64; k++) {
        const int mm = w * 64 + k;
        float p = prob[mm];
        uint2 v = Ec[(size_t)mm * 32 + lane];
        float2 f0 = __half22float2(*reinterpret_cast<__half2*>(&v.x));
        float2 f1 = __half22float2(*reinterpret_cast<__half2*>(&v.y));
        acc.x += p * f0.x; acc.y += p * f0.y; acc.z += p * f1.x; acc.w += p * f1.y;
    }
    wpart[w][lane] = acc;
    __syncthreads();
    if (tid < 32) {
        float4 a = wpart[0][tid];
#pragma unroll
        for (int i = 1; i < 4; i++) {
            float4 c = wpart[i][tid];
            a.x += c.x; a.y += c.y; a.z += c.z; a.w += c.w;
        }
        float4 uu = us[tid];
        a.x += uu.x; a.y += uu.y; a.z += uu.z; a.w += uu.w;
        ((float4*)dst)[tid] = a;
    }
}

// ---------------------------------------------------------------------------
// L1: convert table C1 (tbl 0)
// ---------------------------------------------------------------------------
__global__ void __launch_bounds__(256) conv0_kernel(const float* __restrict__ C) {
    size_t i = (size_t)blockIdx.x * 256 + threadIdx.x;
    if (i < TBL_ITEMS8) convert_item(C, 0, i);
}

// ---------------------------------------------------------------------------
// L2: gather t0 (blocks 0..1023) || convert C2 (blocks 1024..1535)
// ---------------------------------------------------------------------------
__global__ void __launch_bounds__(128) k2_kernel(const int* __restrict__ story,
                                                 const float* __restrict__ C) {
    if (blockIdx.x < 1024) {
        const int w = blockIdx.x * 4 + (threadIdx.x >> 5);
        gather_unit(story, 0, w / MEM, w % MEM, threadIdx.x & 31);
    } else {
        size_t i = (size_t)(blockIdx.x - 1024) * 128 + threadIdx.x;
        const size_t stride = 512 * 128;
        for (; i < TBL_ITEMS8; i += stride) convert_item(C, 1, i);
    }
}

// ---------------------------------------------------------------------------
// L3: hop0 (blocks 0..15) || gather t1 (16..1039) || convert C3 (1040..1551)
// ---------------------------------------------------------------------------
__global__ void __launch_bounds__(128) k3_kernel(const int* __restrict__ story,
                                                 const float* __restrict__ C) {
    if (blockIdx.x < 16) {
        hop0_128(blockIdx.x);
    } else if (blockIdx.x < 1040) {
        const int w = (blockIdx.x - 16) * 4 + (threadIdx.x >> 5);
        gather_unit(story, 1, w / MEM, w % MEM, threadIdx.x & 31);
    } else {
        size_t i = (size_t)(blockIdx.x - 1040) * 128 + threadIdx.x;
        const size_t stride = 512 * 128;
        for (; i < TBL_ITEMS8; i += stride) convert_item(C, 2, i);
    }
}

// ---------------------------------------------------------------------------
// L4: hop1 (blocks 0..15, u += attn(E0,E1)) || gather t2 (16..1039)
// ---------------------------------------------------------------------------
__global__ void __launch_bounds__(128) k4_kernel(const int* __restrict__ story) {
    if (blockIdx.x < 16) {
        hop_128(1, blockIdx.x, g_u[blockIdx.x]);
    } else {
        const int w = (blockIdx.x - 16) * 4 + (threadIdx.x >> 5);
        gather_unit(story, 2, w / MEM, w % MEM, threadIdx.x & 31);
    }
}

// ---------------------------------------------------------------------------
// L5: hop2 -> out
// ---------------------------------------------------------------------------
__global__ void __launch_bounds__(128) k5_kernel(float* __restrict__ out) {
    hop_128(2, blockIdx.x, out + (size_t)blockIdx.x * EMB);
}

extern "C" void kernel_launch(void* const* d_in, const int* in_sizes, int n_in,
                              void* d_out, int out_size) {
    const int*   story = (const int*)d_in[0];   // (256, 16, 64) int32
    const float* C     = (const float*)d_in[1]; // (4, 50257, 128) fp32
    float*       out   = (float*)d_out;         // (16, 128) fp32

    (void)in_sizes; (void)n_in; (void)out_size;

    conv0_kernel<<<(int)((TBL_ITEMS8 + 255) / 256), 256>>>(C);
    k2_kernel<<<1536, 128>>>(story, C);
    k3_kernel<<<1552, 128>>>(story, C);
    k4_kernel<<<1040, 128>>>(story);
    k5_kernel<<<BATCH, 128>>>(out);
}

// round 8
// speedup vs baseline: 1.1992x; 1.1992x over previous
#include <cuda_runtime.h>

// Problem constants
#define HOPS  3
#define VOCAB 50257
#define EMB   128
#define MEM   256   // memory slots (M)
#define BATCH 16    // batch (B)
#define SENT  64    // sentence length (S)

#define TBL_ELEMS ((size_t)VOCAB * EMB)

// E[t][b][m][d] = sum_s C[t+1][story[m][b][s]][d], fp32 (6.3 MB).
// (C0 is never needed: hop-0 softmax of zero logits is exactly uniform.)
__device__ __align__(16) float g_E[3][BATCH][MEM][EMB];
// hop state u, fp32
__device__ __align__(16) float g_u[BATCH][EMB];

// ---------------------------------------------------------------------------
// Gather-sum one (t,b,m) unit with one warp, straight from the fp32 table.
// 64 token rows of 512B each, fully coalesced LDG.128 across the warp.
// ---------------------------------------------------------------------------
__device__ __forceinline__ void gather_unit(const int* __restrict__ story,
                                            const float* __restrict__ C,
                                            int t, int b, int m, int lane) {
    const int* toks = story + ((size_t)m * BATCH + b) * SENT;
    const int tok_lo = toks[lane];
    const int tok_hi = toks[lane + 32];

    const float4* __restrict__ tab =
        (const float4*)(C + (size_t)(t + 1) * TBL_ELEMS);

    float4 a0 = make_float4(0.f, 0.f, 0.f, 0.f);
    float4 a1 = make_float4(0.f, 0.f, 0.f, 0.f);

#pragma unroll
    for (int s = 0; s < 32; s++) {
        int tok = __shfl_sync(0xffffffffu, tok_lo, s);
        float4 v = __ldg(tab + (size_t)tok * (EMB / 4) + lane);
        a0.x += v.x; a0.y += v.y; a0.z += v.z; a0.w += v.w;
    }
#pragma unroll
    for (int s = 0; s < 32; s++) {
        int tok = __shfl_sync(0xffffffffu, tok_hi, s);
        float4 v = __ldg(tab + (size_t)tok * (EMB / 4) + lane);
        a1.x += v.x; a1.y += v.y; a1.z += v.z; a1.w += v.w;
    }

    float4 acc = make_float4(a0.x + a1.x, a0.y + a1.y, a0.z + a1.z, a0.w + a1.w);
    ((float4*)g_E[t][b][m])[lane] = acc;
}

// ---------------------------------------------------------------------------
// hop0 for batch b, 256 threads: g_u[b] = mean_m E0[b][m]
// ---------------------------------------------------------------------------
__device__ __forceinline__ void hop0_256(int b) {
    __shared__ float4 wp[8][32];
    const int tid = threadIdx.x, w = tid >> 5, lane = tid & 31;
    const float4* __restrict__ E0 = (const float4*)g_E[0][b];

    float4 acc = make_float4(0.f, 0.f, 0.f, 0.f);
#pragma unroll 4
    for (int k = 0; k < 32; k++) {
        float4 v = E0[(size_t)(w * 32 + k) * 32 + lane];
        acc.x += v.x; acc.y += v.y; acc.z += v.z; acc.w += v.w;
    }
    wp[w][lane] = acc;
    __syncthreads();
    if (tid < 32) {
        float4 a = wp[0][tid];
#pragma unroll
        for (int i = 1; i < 8; i++) {
            float4 c = wp[i][tid];
            a.x += c.x; a.y += c.y; a.z += c.z; a.w += c.w;
        }
        a.x *= (1.f / MEM); a.y *= (1.f / MEM); a.z *= (1.f / MEM); a.w *= (1.f / MEM);
        ((float4*)g_u[b])[tid] = a;
    }
}

// ---------------------------------------------------------------------------
// One attention hop for batch b, 256 threads:
//   prob = softmax_m( E[hp-1][b] . u ) ;  dst = u + sum_m prob[m] * E[hp][b][m]
// ---------------------------------------------------------------------------
__device__ __forceinline__ void hop_256(int hp, int b, float* __restrict__ dst) {
    __shared__ float4 us[32];
    __shared__ float  prob[MEM];
    __shared__ float4 wp[8][32];
    __shared__ float  red[8];

    const int tid = threadIdx.x, w = tid >> 5, lane = tid & 31;
    const float4* __restrict__ Ep = (const float4*)g_E[hp - 1][b];
    const float4* __restrict__ Ec = (const float4*)g_E[hp][b];

    if (tid < 32) us[tid] = ((const float4*)g_u[b])[tid];
    __syncthreads();

    // logits: 4 lanes per slot; 64 slots per pass, 4 passes
    const int q = lane & 3, sl = lane >> 2;
#pragma unroll
    for (int pass = 0; pass < 4; pass++) {
        const int m = pass * 64 + w * 8 + sl;
        float pd = 0.f;
#pragma unroll
        for (int j = 0; j < 8; j++) {
            float4 e  = Ep[(size_t)m * 32 + q + 4 * j];
            float4 uu = us[q + 4 * j];
            pd += e.x * uu.x + e.y * uu.y + e.z * uu.z + e.w * uu.w;
        }
        pd += __shfl_xor_sync(0xffffffffu, pd, 1);
        pd += __shfl_xor_sync(0xffffffffu, pd, 2);
        if (q == 0) prob[m] = pd;
    }
    __syncthreads();

    // softmax over prob[0..255], one value per thread
    {
        float x = prob[tid];
        float mx = x;
#pragma unroll
        for (int off = 16; off; off >>= 1)
            mx = fmaxf(mx, __shfl_xor_sync(0xffffffffu, mx, off));
        if (lane == 0) red[w] = mx;
        __syncthreads();
        mx = red[0];
#pragma unroll
        for (int i = 1; i < 8; i++) mx = fmaxf(mx, red[i]);
        __syncthreads();

        float ev = __expf(x - mx);
        float sv = ev;
#pragma unroll
        for (int off = 16; off; off >>= 1)
            sv += __shfl_xor_sync(0xffffffffu, sv, off);
        if (lane == 0) red[w] = sv;
        __syncthreads();
        float tot = red[0];
#pragma unroll
        for (int i = 1; i < 8; i++) tot += red[i];

        prob[tid] = ev / tot;
        __syncthreads();
    }

    // weighted sum: warp w owns 32 slots
    float4 acc = make_float4(0.f, 0.f, 0.f, 0.f);
#pragma unroll 4
    for (int k = 0; k < 32; k++) {
        const int mm = w * 32 + k;
        float p = prob[mm];
        float4 v = Ec[(size_t)mm * 32 + lane];
        acc.x += p * v.x; acc.y += p * v.y; acc.z += p * v.z; acc.w += p * v.w;
    }
    wp[w][lane] = acc;
    __syncthreads();
    if (tid < 32) {
        float4 a = wp[0][tid];
#pragma unroll
        for (int i = 1; i < 8; i++) {
            float4 c = wp[i][tid];
            a.x += c.x; a.y += c.y; a.z += c.z; a.w += c.w;
        }
        float4 uu = us[tid];
        a.x += uu.x; a.y += uu.y; a.z += uu.z; a.w += uu.w;
        ((float4*)dst)[tid] = a;
    }
}

// ---------------------------------------------------------------------------
// K1: gather t0.  512 blocks x 8 warps = 4096 units.
// ---------------------------------------------------------------------------
__global__ void __launch_bounds__(256) k1_kernel(const int* __restrict__ story,
                                                 const float* __restrict__ C) {
    const int w = blockIdx.x * 8 + (threadIdx.x >> 5);
    gather_unit(story, C, 0, w / MEM, w % MEM, threadIdx.x & 31);
}

// ---------------------------------------------------------------------------
// K2: hop0 (blocks 0..15) || gather t1 (blocks 16..527)
// ---------------------------------------------------------------------------
__global__ void __launch_bounds__(256) k2_kernel(const int* __restrict__ story,
                                                 const float* __restrict__ C) {
    if (blockIdx.x < 16) {
        hop0_256(blockIdx.x);
    } else {
        const int w = (blockIdx.x - 16) * 8 + (threadIdx.x >> 5);
        gather_unit(story, C, 1, w / MEM, w % MEM, threadIdx.x & 31);
    }
}

// ---------------------------------------------------------------------------
// K3: hop1 (blocks 0..15) || gather t2 (blocks 16..527)
// ---------------------------------------------------------------------------
__global__ void __launch_bounds__(256) k3_kernel(const int* __restrict__ story,
                                                 const float* __restrict__ C) {
    if (blockIdx.x < 16) {
        hop_256(1, blockIdx.x, g_u[blockIdx.x]);
    } else {
        const int w = (blockIdx.x - 16) * 8 + (threadIdx.x >> 5);
        gather_unit(story, C, 2, w / MEM, w % MEM, threadIdx.x & 31);
    }
}

// ---------------------------------------------------------------------------
// K4: hop2 -> out
// ---------------------------------------------------------------------------
__global__ void __launch_bounds__(256) k4_kernel(float* __restrict__ out) {
    hop_256(2, blockIdx.x, out + (size_t)blockIdx.x * EMB);
}

extern "C" void kernel_launch(void* const* d_in, const int* in_sizes, int n_in,
                              void* d_out, int out_size) {
    const int*   story = (const int*)d_in[0];   // (256, 16, 64) int32
    const float* C     = (const float*)d_in[1]; // (4, 50257, 128) fp32
    float*       out   = (float*)d_out;         // (16, 128) fp32

    (void)in_sizes; (void)n_in; (void)out_size;

    k1_kernel<<<512, 256>>>(story, C);
    k2_kernel<<<528, 256>>>(story, C);
    k3_kernel<<<528, 256>>>(story, C);
    k4_kernel<<<BATCH, 256>>>(out);
}